// round 1
// baseline (speedup 1.0000x reference)
#include <cuda_runtime.h>
#include <cuda_bf16.h>
#include <cstdint>

// Problem shape (fixed for this dataset instance)
#define BDIM 4
#define NDIM 512
#define MDIM 512            // reduction dim
#define KDIM 256            // output cols
#define MROWS (BDIM*NDIM)   // 2048 output rows

// GEMM tiling
#define BM 64
#define BN 64
#define BK 64
#define LDS 72              // padded smem row stride (bf16 elems): 144B, 16B aligned

// Scratch (allocation-free rule: __device__ globals)
__device__ __align__(16) __nv_bfloat16 g_xq[MROWS * MDIM];   // 2 MB
__device__ __align__(16) __nv_bfloat16 g_wq[KDIM * MDIM];    // 256 KB
__device__ float g_rowsum[MROWS];
__device__ float g_colsum[KDIM];

// ---------------------------------------------------------------------------
// Quantize: q = clip(rint(x/s + zp), -128, 127), stored exactly as bf16.
// Matches jnp.round (round-half-even) via rintf under RN.
// ---------------------------------------------------------------------------
__device__ __forceinline__ float quantize1(float v, float s, float zp) {
    float q = rintf(__fadd_rn(__fdiv_rn(v, s), zp));
    return fminf(fmaxf(q, -128.0f), 127.0f);
}

// One warp per row of 512 floats. 8 warps/block.
__global__ void quant_x_kernel(const float* __restrict__ x,
                               const float* __restrict__ xs_p,
                               const float* __restrict__ xzp_p) {
    int warp = threadIdx.x >> 5;
    int lane = threadIdx.x & 31;
    int row = blockIdx.x * 8 + warp;
    if (row >= MROWS) return;
    float s = xs_p[0], zp = xzp_p[0];
    const float4* src = reinterpret_cast<const float4*>(x + (size_t)row * MDIM);
    uint2* dst = reinterpret_cast<uint2*>(g_xq + (size_t)row * MDIM);
    float sum = 0.0f;
#pragma unroll
    for (int i = 0; i < 4; i++) {
        int c = i * 32 + lane;              // float4 index within row (128 per row)
        float4 v = src[c];
        float q0 = quantize1(v.x, s, zp);
        float q1 = quantize1(v.y, s, zp);
        float q2 = quantize1(v.z, s, zp);
        float q3 = quantize1(v.w, s, zp);
        sum += q0 + q1 + q2 + q3;
        __nv_bfloat162 p01 = __floats2bfloat162_rn(q0, q1);
        __nv_bfloat162 p23 = __floats2bfloat162_rn(q2, q3);
        uint2 packed;
        packed.x = *reinterpret_cast<uint32_t*>(&p01);
        packed.y = *reinterpret_cast<uint32_t*>(&p23);
        dst[c] = packed;
    }
#pragma unroll
    for (int off = 16; off > 0; off >>= 1)
        sum += __shfl_xor_sync(0xFFFFFFFFu, sum, off);
    if (lane == 0) g_rowsum[row] = sum;
}

__global__ void quant_w_kernel(const float* __restrict__ w,
                               const float* __restrict__ ws_p,
                               const float* __restrict__ wzp_p) {
    int warp = threadIdx.x >> 5;
    int lane = threadIdx.x & 31;
    int row = blockIdx.x * 8 + warp;  // row = k index
    if (row >= KDIM) return;
    float s = ws_p[0], zp = wzp_p[0];
    const float4* src = reinterpret_cast<const float4*>(w + (size_t)row * MDIM);
    uint2* dst = reinterpret_cast<uint2*>(g_wq + (size_t)row * MDIM);
    float sum = 0.0f;
#pragma unroll
    for (int i = 0; i < 4; i++) {
        int c = i * 32 + lane;
        float4 v = src[c];
        float q0 = quantize1(v.x, s, zp);
        float q1 = quantize1(v.y, s, zp);
        float q2 = quantize1(v.z, s, zp);
        float q3 = quantize1(v.w, s, zp);
        sum += q0 + q1 + q2 + q3;
        __nv_bfloat162 p01 = __floats2bfloat162_rn(q0, q1);
        __nv_bfloat162 p23 = __floats2bfloat162_rn(q2, q3);
        uint2 packed;
        packed.x = *reinterpret_cast<uint32_t*>(&p01);
        packed.y = *reinterpret_cast<uint32_t*>(&p23);
        dst[c] = packed;
    }
#pragma unroll
    for (int off = 16; off > 0; off >>= 1)
        sum += __shfl_xor_sync(0xFFFFFFFFu, sum, off);
    if (lane == 0) g_colsum[row] = sum;
}

// ---------------------------------------------------------------------------
// GEMM: out[row, k] = (sum_m xq*wq - wzp*rowsum - xzp*colsum + M*xzp*wzp)*xs*ws
// bf16 mma.sync m16n8k16 with fp32 accum (exact for these integer magnitudes).
// Block: 128 threads (4 warps, 2x2 warp grid), tile BM=64 x BN=64, BK=64.
// ---------------------------------------------------------------------------
__device__ __forceinline__ uint32_t smem_u32(const void* p) {
    return (uint32_t)__cvta_generic_to_shared(p);
}

__device__ __forceinline__ void ldsm_x4(uint32_t& r0, uint32_t& r1,
                                        uint32_t& r2, uint32_t& r3, uint32_t addr) {
    asm volatile("ldmatrix.sync.aligned.m8n8.x4.shared.b16 {%0,%1,%2,%3}, [%4];"
                 : "=r"(r0), "=r"(r1), "=r"(r2), "=r"(r3) : "r"(addr));
}

__device__ __forceinline__ void mma16816(float& c0, float& c1, float& c2, float& c3,
                                         uint32_t a0, uint32_t a1, uint32_t a2, uint32_t a3,
                                         uint32_t b0, uint32_t b1) {
    asm volatile(
        "mma.sync.aligned.m16n8k16.row.col.f32.bf16.bf16.f32 "
        "{%0,%1,%2,%3}, {%4,%5,%6,%7}, {%8,%9}, {%0,%1,%2,%3};"
        : "+f"(c0), "+f"(c1), "+f"(c2), "+f"(c3)
        : "r"(a0), "r"(a1), "r"(a2), "r"(a3), "r"(b0), "r"(b1));
}

__global__ __launch_bounds__(128, 4)
void lut_gemm_kernel(float* __restrict__ out,
                     const float* __restrict__ xs_p, const float* __restrict__ xzp_p,
                     const float* __restrict__ ws_p, const float* __restrict__ wzp_p) {
    __shared__ __nv_bfloat16 sA[BM * LDS];
    __shared__ __nv_bfloat16 sB[BN * LDS];

    const int tid  = threadIdx.x;
    const int lane = tid & 31;
    const int warp = tid >> 5;
    const int warp_m = warp >> 1;       // 0..1, 32 rows each
    const int warp_n = warp & 1;        // 0..1, 32 cols each

    const int m0 = blockIdx.x * BM;
    const int n0 = blockIdx.y * BN;

    float acc[2][4][4];
#pragma unroll
    for (int i = 0; i < 2; i++)
#pragma unroll
        for (int j = 0; j < 4; j++)
#pragma unroll
            for (int q = 0; q < 4; q++) acc[i][j][q] = 0.0f;

    // ldmatrix source addresses (fixed per thread, offset by ks each step)
    // A: warp covers rows [warp_m*32, +32); two 16-row frags
    const int a_row = warp_m * 32 + (lane & 15);
    const int a_colh = (lane >> 4) * 8;
    // B: warp covers cols(n) [warp_n*32, +32); x4 loads 2 n-blocks x 2 k-halves
    const int b_g = lane >> 3;                   // 0..3
    const int b_nb = b_g >> 1;                   // 0..1 (n-block within pair)
    const int b_kh = (b_g & 1) * 8;              // k-half
    const int b_row = warp_n * 32 + b_nb * 8 + (lane & 7);

    const uint32_t sA_base = smem_u32(sA);
    const uint32_t sB_base = smem_u32(sB);

    for (int kt = 0; kt < MDIM / BK; kt++) {
        // --- load tiles into smem (vectorized, 8 bf16 per thread per step) ---
        const int kbase = kt * BK;
#pragma unroll
        for (int i = 0; i < 4; i++) {
            int v = tid + i * 128;          // 0..511
            int r = v >> 3;                 // 0..63
            int cv = v & 7;                 // vec8 within row
            uint4 da = *reinterpret_cast<const uint4*>(
                g_xq + (size_t)(m0 + r) * MDIM + kbase + cv * 8);
            *reinterpret_cast<uint4*>(&sA[r * LDS + cv * 8]) = da;
            uint4 db = *reinterpret_cast<const uint4*>(
                g_wq + (size_t)(n0 + r) * MDIM + kbase + cv * 8);
            *reinterpret_cast<uint4*>(&sB[r * LDS + cv * 8]) = db;
        }
        __syncthreads();

#pragma unroll
        for (int ks = 0; ks < BK / 16; ks++) {
            const int kk = ks * 16;
            // A fragments: 2 x (16x16)
            uint32_t a[2][4];
#pragma unroll
            for (int mi = 0; mi < 2; mi++) {
                uint32_t addr = sA_base +
                    ((a_row + mi * 16) * LDS + kk + a_colh) * 2;
                ldsm_x4(a[mi][0], a[mi][1], a[mi][2], a[mi][3], addr);
            }
            // B fragments: 4 n-blocks of 8, via 2 x4 loads
            uint32_t b[4][2];
#pragma unroll
            for (int np = 0; np < 2; np++) {    // n-block pairs {0,1},{2,3}
                uint32_t r0, r1, r2, r3;
                uint32_t addr = sB_base +
                    ((b_row + np * 16) * LDS + kk + b_kh) * 2;
                ldsm_x4(r0, r1, r2, r3, addr);
                b[np * 2 + 0][0] = r0; b[np * 2 + 0][1] = r1;
                b[np * 2 + 1][0] = r2; b[np * 2 + 1][1] = r3;
            }
#pragma unroll
            for (int mi = 0; mi < 2; mi++)
#pragma unroll
                for (int ni = 0; ni < 4; ni++)
                    mma16816(acc[mi][ni][0], acc[mi][ni][1],
                             acc[mi][ni][2], acc[mi][ni][3],
                             a[mi][0], a[mi][1], a[mi][2], a[mi][3],
                             b[ni][0], b[ni][1]);
        }
        __syncthreads();
    }

    // --- epilogue: zero-point corrections + rescale ---
    const float xs  = xs_p[0];
    const float xzp = xzp_p[0];
    const float ws  = ws_p[0];
    const float wzp = wzp_p[0];
    const float sc  = xs * ws;
    const float kconst = (float)MDIM * xzp * wzp;

#pragma unroll
    for (int mi = 0; mi < 2; mi++) {
        int row_base = m0 + warp_m * 32 + mi * 16 + (lane >> 2);
#pragma unroll
        for (int ni = 0; ni < 4; ni++) {
            int col = n0 + warp_n * 32 + ni * 8 + (lane & 3) * 2;
            float cs0 = g_colsum[col];
            float cs1 = g_colsum[col + 1];
#pragma unroll
            for (int half = 0; half < 2; half++) {
                int row = row_base + half * 8;
                float rs = g_rowsum[row];
                float corr = -wzp * rs + kconst;
                float v0 = (acc[mi][ni][half * 2 + 0] + corr - xzp * cs0) * sc;
                float v1 = (acc[mi][ni][half * 2 + 1] + corr - xzp * cs1) * sc;
                out[(size_t)row * KDIM + col]     = v0;
                out[(size_t)row * KDIM + col + 1] = v1;
            }
        }
    }
}

// ---------------------------------------------------------------------------
// Launch. Input order per metadata: x, w, lut, x_scale, x_zero_point,
// w_scale, w_zero_point. LUT is mathematically the exact int8 product table,
// so it is not needed.
// ---------------------------------------------------------------------------
extern "C" void kernel_launch(void* const* d_in, const int* in_sizes, int n_in,
                              void* d_out, int out_size) {
    const float* x   = (const float*)d_in[0];
    const float* w   = (const float*)d_in[1];
    const float* xs  = (const float*)d_in[3];
    const float* xzp = (const float*)d_in[4];
    const float* ws  = (const float*)d_in[5];
    const float* wzp = (const float*)d_in[6];
    float* out = (float*)d_out;

    quant_x_kernel<<<MROWS / 8, 256>>>(x, xs, xzp);
    quant_w_kernel<<<KDIM / 8, 256>>>(w, ws, wzp);

    dim3 grid(MROWS / BM, KDIM / BN);   // 32 x 4 = 128 blocks
    lut_gemm_kernel<<<grid, 128>>>(out, xs, xzp, ws, wzp);
}

// round 2
// speedup vs baseline: 1.3219x; 1.3219x over previous
#include <cuda_runtime.h>
#include <cuda_bf16.h>
#include <cstdint>

// Problem shape (fixed for this dataset instance)
#define MDIM 512            // reduction dim
#define KDIM 256            // output cols (w rows)
#define MROWS 2048          // output rows (B*N)
#define TOTROWS (MROWS + KDIM)

// GEMM tiling
#define BM 64
#define BN 64
#define BK 64
#define LDS 72              // padded smem row stride (bf16): 144B (16B-aligned rows)
#define STAGES 2

// Scratch (allocation-free rule: __device__ globals)
__device__ __align__(16) __nv_bfloat16 g_xq[MROWS * MDIM];   // 2 MB
__device__ __align__(16) __nv_bfloat16 g_wq[KDIM * MDIM];    // 256 KB
__device__ float g_rowsum[MROWS];
__device__ float g_colsum[KDIM];

// ---------------------------------------------------------------------------
// quantize: q = clip(rint(v/s + zp), -128, 127)  (exact in bf16)
// ---------------------------------------------------------------------------
__device__ __forceinline__ float quantize1(float v, float s, float zp) {
    float q = rintf(__fadd_rn(__fdiv_rn(v, s), zp));
    return fminf(fmaxf(q, -128.0f), 127.0f);
}

// ---------------------------------------------------------------------------
// Fused quantize kernel: rows [0,2048) = x, rows [2048,2304) = w.
// 2 rows per block; 4 warps per row, 1 float4 per thread. High occupancy,
// MLP-rich -> DRAM-bandwidth bound.
// ---------------------------------------------------------------------------
__global__ __launch_bounds__(256)
void quant_all_kernel(const float* __restrict__ x,
                      const float* __restrict__ w,
                      const float* __restrict__ xs_p, const float* __restrict__ xzp_p,
                      const float* __restrict__ ws_p, const float* __restrict__ wzp_p) {
    __shared__ float spart[8];
    const int tid  = threadIdx.x;
    const int lane = tid & 31;
    const int wid  = tid >> 5;
    const int row  = blockIdx.x * 2 + (tid >> 7);     // 0..2303
    const int q4   = ((tid >> 5) & 3) * 32 + lane;    // float4 index in row (0..127)

    const bool isX = row < MROWS;
    const float s  = isX ? xs_p[0]  : ws_p[0];
    const float zp = isX ? xzp_p[0] : wzp_p[0];
    const float* src = isX ? (x + (size_t)row * MDIM)
                           : (w + (size_t)(row - MROWS) * MDIM);
    __nv_bfloat16* dst = isX ? (g_xq + (size_t)row * MDIM)
                             : (g_wq + (size_t)(row - MROWS) * MDIM);

    float4 v = reinterpret_cast<const float4*>(src)[q4];
    float q0 = quantize1(v.x, s, zp);
    float q1 = quantize1(v.y, s, zp);
    float q2 = quantize1(v.z, s, zp);
    float q3 = quantize1(v.w, s, zp);
    __nv_bfloat162 p01 = __floats2bfloat162_rn(q0, q1);
    __nv_bfloat162 p23 = __floats2bfloat162_rn(q2, q3);
    uint2 packed;
    packed.x = *reinterpret_cast<uint32_t*>(&p01);
    packed.y = *reinterpret_cast<uint32_t*>(&p23);
    reinterpret_cast<uint2*>(dst)[q4] = packed;

    float sum = q0 + q1 + q2 + q3;
#pragma unroll
    for (int off = 16; off > 0; off >>= 1)
        sum += __shfl_xor_sync(0xFFFFFFFFu, sum, off);
    if (lane == 0) spart[wid] = sum;
    __syncthreads();
    if (tid < 2) {
        int r = blockIdx.x * 2 + tid;
        float total = spart[tid * 4 + 0] + spart[tid * 4 + 1] +
                      spart[tid * 4 + 2] + spart[tid * 4 + 3];
        if (r < MROWS) g_rowsum[r] = total;
        else           g_colsum[r - MROWS] = total;
    }
}

// ---------------------------------------------------------------------------
// GEMM helpers
// ---------------------------------------------------------------------------
__device__ __forceinline__ uint32_t smem_u32(const void* p) {
    return (uint32_t)__cvta_generic_to_shared(p);
}
__device__ __forceinline__ void cp_async16(uint32_t saddr, const void* gptr) {
    asm volatile("cp.async.cg.shared.global [%0], [%1], 16;\n"
                 :: "r"(saddr), "l"(gptr));
}
__device__ __forceinline__ void cp_commit() {
    asm volatile("cp.async.commit_group;\n");
}
template <int N>
__device__ __forceinline__ void cp_wait() {
    asm volatile("cp.async.wait_group %0;\n" :: "n"(N));
}
__device__ __forceinline__ void ldsm_x4(uint32_t& r0, uint32_t& r1,
                                        uint32_t& r2, uint32_t& r3, uint32_t addr) {
    asm volatile("ldmatrix.sync.aligned.m8n8.x4.shared.b16 {%0,%1,%2,%3}, [%4];"
                 : "=r"(r0), "=r"(r1), "=r"(r2), "=r"(r3) : "r"(addr));
}
__device__ __forceinline__ void mma16816(float& c0, float& c1, float& c2, float& c3,
                                         uint32_t a0, uint32_t a1, uint32_t a2, uint32_t a3,
                                         uint32_t b0, uint32_t b1) {
    asm volatile(
        "mma.sync.aligned.m16n8k16.row.col.f32.bf16.bf16.f32 "
        "{%0,%1,%2,%3}, {%4,%5,%6,%7}, {%8,%9}, {%0,%1,%2,%3};"
        : "+f"(c0), "+f"(c1), "+f"(c2), "+f"(c3)
        : "r"(a0), "r"(a1), "r"(a2), "r"(a3), "r"(b0), "r"(b1));
}

// ---------------------------------------------------------------------------
// Pipelined GEMM: 256 threads, warp grid 2x4, warp tile 32x16, BK=64,
// 2-stage cp.async double buffering. One __syncthreads per k-tile.
// ---------------------------------------------------------------------------
__global__ __launch_bounds__(256, 1)
void lut_gemm_kernel(float* __restrict__ out,
                     const float* __restrict__ xs_p, const float* __restrict__ xzp_p,
                     const float* __restrict__ ws_p, const float* __restrict__ wzp_p) {
    __shared__ __nv_bfloat16 sA[STAGES][BM * LDS];
    __shared__ __nv_bfloat16 sB[STAGES][BN * LDS];

    const int tid  = threadIdx.x;
    const int lane = tid & 31;
    const int warp = tid >> 5;
    const int warp_m = warp >> 2;       // 0..1 (32 rows each)
    const int warp_n = warp & 3;        // 0..3 (16 cols each)

    const int m0 = blockIdx.x * BM;
    const int n0 = blockIdx.y * BN;

    float acc[2][2][4];
#pragma unroll
    for (int i = 0; i < 2; i++)
#pragma unroll
        for (int j = 0; j < 2; j++)
#pragma unroll
            for (int q = 0; q < 4; q++) acc[i][j][q] = 0.0f;

    // cp.async source/dest mapping: 512 16B-chunks per tile per operand,
    // 2 chunks of A + 2 of B per thread.
    const int c_r0 = tid >> 3;            // 0..31
    const int c_c  = tid & 7;             // chunk col (16B units)

    auto issue_stage = [&](int kt, int stg) {
        const int kbase = kt * BK;
#pragma unroll
        for (int i = 0; i < 2; i++) {
            int r = c_r0 + i * 32;
            cp_async16(smem_u32(&sA[stg][r * LDS + c_c * 8]),
                       g_xq + (size_t)(m0 + r) * MDIM + kbase + c_c * 8);
        }
#pragma unroll
        for (int i = 0; i < 2; i++) {
            int r = c_r0 + i * 32;
            cp_async16(smem_u32(&sB[stg][r * LDS + c_c * 8]),
                       g_wq + (size_t)(n0 + r) * MDIM + kbase + c_c * 8);
        }
        cp_commit();
    };

    issue_stage(0, 0);

    // ldmatrix lane addressing
    const int a_row  = warp_m * 32 + (lane & 15);
    const int a_colh = (lane >> 4) * 8;
    const int b_g    = lane >> 3;                       // 0..3
    const int b_row  = warp_n * 16 + (b_g >> 1) * 8 + (lane & 7);
    const int b_kh   = (b_g & 1) * 8;

    const int NTILES = MDIM / BK;   // 8
    for (int kt = 0; kt < NTILES; kt++) {
        const int stg = kt & 1;
        if (kt + 1 < NTILES) {
            // overlap: next tile loads fly while we MMA this one
            issue_stage(kt + 1, stg ^ 1);
            cp_wait<1>();           // stage kt complete
        } else {
            cp_wait<0>();
        }
        __syncthreads();

        const uint32_t sA_base = smem_u32(sA[stg]);
        const uint32_t sB_base = smem_u32(sB[stg]);
#pragma unroll
        for (int ks = 0; ks < BK / 16; ks++) {
            const int kk = ks * 16;
            uint32_t a[2][4];
#pragma unroll
            for (int mi = 0; mi < 2; mi++) {
                uint32_t addr = sA_base + ((a_row + mi * 16) * LDS + kk + a_colh) * 2;
                ldsm_x4(a[mi][0], a[mi][1], a[mi][2], a[mi][3], addr);
            }
            uint32_t b[2][2];
            {
                uint32_t r0, r1, r2, r3;
                uint32_t addr = sB_base + (b_row * LDS + kk + b_kh) * 2;
                ldsm_x4(r0, r1, r2, r3, addr);
                b[0][0] = r0; b[0][1] = r1;
                b[1][0] = r2; b[1][1] = r3;
            }
#pragma unroll
            for (int mi = 0; mi < 2; mi++)
#pragma unroll
                for (int ni = 0; ni < 2; ni++)
                    mma16816(acc[mi][ni][0], acc[mi][ni][1],
                             acc[mi][ni][2], acc[mi][ni][3],
                             a[mi][0], a[mi][1], a[mi][2], a[mi][3],
                             b[ni][0], b[ni][1]);
        }
        __syncthreads();
    }

    // --- epilogue: zero-point corrections + rescale ---
    const float xs  = xs_p[0];
    const float xzp = xzp_p[0];
    const float ws  = ws_p[0];
    const float wzp = wzp_p[0];
    const float sc  = xs * ws;
    const float kconst = (float)MDIM * xzp * wzp;

#pragma unroll
    for (int mi = 0; mi < 2; mi++) {
        int row_base = m0 + warp_m * 32 + mi * 16 + (lane >> 2);
#pragma unroll
        for (int ni = 0; ni < 2; ni++) {
            int col = n0 + warp_n * 16 + ni * 8 + (lane & 3) * 2;
            float cs0 = g_colsum[col];
            float cs1 = g_colsum[col + 1];
#pragma unroll
            for (int half = 0; half < 2; half++) {
                int row = row_base + half * 8;
                float rs = g_rowsum[row];
                float corr = -wzp * rs + kconst;
                float v0 = (acc[mi][ni][half * 2 + 0] + corr - xzp * cs0) * sc;
                float v1 = (acc[mi][ni][half * 2 + 1] + corr - xzp * cs1) * sc;
                float2 v2 = make_float2(v0, v1);
                *reinterpret_cast<float2*>(out + (size_t)row * KDIM + col) = v2;
            }
        }
    }
}

// ---------------------------------------------------------------------------
// Launch. Inputs: x, w, lut, x_scale, x_zero_point, w_scale, w_zero_point.
// LUT is exactly the int8 product table -> not needed.
// ---------------------------------------------------------------------------
extern "C" void kernel_launch(void* const* d_in, const int* in_sizes, int n_in,
                              void* d_out, int out_size) {
    const float* x   = (const float*)d_in[0];
    const float* w   = (const float*)d_in[1];
    const float* xs  = (const float*)d_in[3];
    const float* xzp = (const float*)d_in[4];
    const float* ws  = (const float*)d_in[5];
    const float* wzp = (const float*)d_in[6];
    float* out = (float*)d_out;

    quant_all_kernel<<<TOTROWS / 2, 256>>>(x, w, xs, xzp, ws, wzp);

    dim3 grid(MROWS / BM, KDIM / BN);   // 32 x 4 = 128 blocks
    lut_gemm_kernel<<<grid, 256>>>(out, xs, xzp, ws, wzp);
}

// round 3
// speedup vs baseline: 1.3484x; 1.0201x over previous
#include <cuda_runtime.h>
#include <cuda_bf16.h>
#include <cstdint>

// Problem shape (fixed)
#define MDIM 512            // reduction dim
#define KDIM 256            // output cols (w rows)
#define MROWS 2048          // output rows (B*N)
#define TOTROWS (MROWS + KDIM)

// GEMM tiling: full-K-resident smem
#define BM 64
#define BN 32
#define LDSE 520            // smem row stride in bf16 (512 + 8): rows 16B-aligned, swizzle-free conflict avoidance
#define SMEM_ROWS (BM + BN) // 96
#define SMEM_BYTES (SMEM_ROWS * LDSE * 2)   // 99840

// Scratch
__device__ __align__(16) __nv_bfloat16 g_xq[MROWS * MDIM];   // 2 MB
__device__ __align__(16) __nv_bfloat16 g_wq[KDIM * MDIM];    // 256 KB
__device__ float g_rowsum[MROWS];
__device__ float g_colsum[KDIM];

// ---------------------------------------------------------------------------
// quantize: q = clip(rint(v/s + zp), -128, 127)  (exact in bf16)
// ---------------------------------------------------------------------------
__device__ __forceinline__ float quantize1(float v, float s, float zp) {
    float q = rintf(__fadd_rn(__fdiv_rn(v, s), zp));
    return fminf(fmaxf(q, -128.0f), 127.0f);
}

// Fused quantize: rows [0,2048)=x, [2048,2304)=w. 2 rows/block, 4 warps/row.
__global__ __launch_bounds__(256)
void quant_all_kernel(const float* __restrict__ x,
                      const float* __restrict__ w,
                      const float* __restrict__ xs_p, const float* __restrict__ xzp_p,
                      const float* __restrict__ ws_p, const float* __restrict__ wzp_p) {
    __shared__ float spart[8];
    const int tid  = threadIdx.x;
    const int lane = tid & 31;
    const int wid  = tid >> 5;
    const int row  = blockIdx.x * 2 + (tid >> 7);
    const int q4   = ((tid >> 5) & 3) * 32 + lane;

    const bool isX = row < MROWS;
    const float s  = isX ? xs_p[0]  : ws_p[0];
    const float zp = isX ? xzp_p[0] : wzp_p[0];
    const float* src = isX ? (x + (size_t)row * MDIM)
                           : (w + (size_t)(row - MROWS) * MDIM);
    __nv_bfloat16* dst = isX ? (g_xq + (size_t)row * MDIM)
                             : (g_wq + (size_t)(row - MROWS) * MDIM);

    float4 v = reinterpret_cast<const float4*>(src)[q4];
    float q0 = quantize1(v.x, s, zp);
    float q1 = quantize1(v.y, s, zp);
    float q2 = quantize1(v.z, s, zp);
    float q3 = quantize1(v.w, s, zp);
    __nv_bfloat162 p01 = __floats2bfloat162_rn(q0, q1);
    __nv_bfloat162 p23 = __floats2bfloat162_rn(q2, q3);
    uint2 packed;
    packed.x = *reinterpret_cast<uint32_t*>(&p01);
    packed.y = *reinterpret_cast<uint32_t*>(&p23);
    reinterpret_cast<uint2*>(dst)[q4] = packed;

    float sum = q0 + q1 + q2 + q3;
#pragma unroll
    for (int off = 16; off > 0; off >>= 1)
        sum += __shfl_xor_sync(0xFFFFFFFFu, sum, off);
    if (lane == 0) spart[wid] = sum;
    __syncthreads();
    if (tid < 2) {
        int r = blockIdx.x * 2 + tid;
        float total = spart[tid * 4 + 0] + spart[tid * 4 + 1] +
                      spart[tid * 4 + 2] + spart[tid * 4 + 3];
        if (r < MROWS) g_rowsum[r] = total;
        else           g_colsum[r - MROWS] = total;
    }
}

// ---------------------------------------------------------------------------
// GEMM helpers
// ---------------------------------------------------------------------------
__device__ __forceinline__ uint32_t smem_u32(const void* p) {
    return (uint32_t)__cvta_generic_to_shared(p);
}
__device__ __forceinline__ void cp_async16(uint32_t saddr, const void* gptr) {
    asm volatile("cp.async.cg.shared.global [%0], [%1], 16;\n"
                 :: "r"(saddr), "l"(gptr));
}
__device__ __forceinline__ void cp_commit() {
    asm volatile("cp.async.commit_group;\n");
}
template <int N>
__device__ __forceinline__ void cp_wait() {
    asm volatile("cp.async.wait_group %0;\n" :: "n"(N));
}
__device__ __forceinline__ void ldsm_x4(uint32_t& r0, uint32_t& r1,
                                        uint32_t& r2, uint32_t& r3, uint32_t addr) {
    asm volatile("ldmatrix.sync.aligned.m8n8.x4.shared.b16 {%0,%1,%2,%3}, [%4];"
                 : "=r"(r0), "=r"(r1), "=r"(r2), "=r"(r3) : "r"(addr));
}
__device__ __forceinline__ void ldsm_x2(uint32_t& r0, uint32_t& r1, uint32_t addr) {
    asm volatile("ldmatrix.sync.aligned.m8n8.x2.shared.b16 {%0,%1}, [%2];"
                 : "=r"(r0), "=r"(r1) : "r"(addr));
}
__device__ __forceinline__ void mma16816(float& c0, float& c1, float& c2, float& c3,
                                         uint32_t a0, uint32_t a1, uint32_t a2, uint32_t a3,
                                         uint32_t b0, uint32_t b1) {
    asm volatile(
        "mma.sync.aligned.m16n8k16.row.col.f32.bf16.bf16.f32 "
        "{%0,%1,%2,%3}, {%4,%5,%6,%7}, {%8,%9}, {%0,%1,%2,%3};"
        : "+f"(c0), "+f"(c1), "+f"(c2), "+f"(c3)
        : "r"(a0), "r"(a1), "r"(a2), "r"(a3), "r"(b0), "r"(b1));
}

// ---------------------------------------------------------------------------
// Full-resident GEMM: whole K=512 strip of A(64 rows) + B(32 rows) in smem.
// All loads issued up front in 8 K-slice commit groups; incremental waits.
// 256 threads, 8 warps (2m x 4n), warp tile 32x8, 16 FFMA-free regs of acc.
// ---------------------------------------------------------------------------
__global__ __launch_bounds__(256, 2)
void lut_gemm_kernel(float* __restrict__ out,
                     const float* __restrict__ xs_p, const float* __restrict__ xzp_p,
                     const float* __restrict__ ws_p, const float* __restrict__ wzp_p) {
    extern __shared__ __nv_bfloat16 smem[];   // SMEM_ROWS x LDSE

    const int tid  = threadIdx.x;
    const int lane = tid & 31;
    const int warp = tid >> 5;
    const int warp_m = warp >> 2;   // 0..1 (32 rows)
    const int warp_n = warp & 3;    // 0..3 (8 cols)

    const int m0 = blockIdx.x * BM;
    const int n0 = blockIdx.y * BN;

    // ---- issue ALL loads: 8 groups, one per 64-elem K slice ----
    // Per group: 96 rows x 8 chunks(16B) = 768 chunks = 3 per thread.
    {
        const int r = (tid * 3) / 8 >= 0 ? 0 : 0; // (placate compiler ordering)
#pragma unroll
        for (int kt = 0; kt < 8; kt++) {
#pragma unroll
            for (int i = 0; i < 3; i++) {
                int idx = tid + i * 256;          // 0..767
                int rr  = idx >> 3;               // 0..95
                int cc  = (idx & 7) + kt * 8;     // chunk col 0..63
                const __nv_bfloat16* src = (rr < BM)
                    ? (g_xq + (size_t)(m0 + rr) * MDIM + cc * 8)
                    : (g_wq + (size_t)(n0 + rr - BM) * MDIM + cc * 8);
                cp_async16(smem_u32(&smem[rr * LDSE + cc * 8]), src);
            }
            cp_commit();
        }
        (void)r;
    }

    float acc[2][4];
#pragma unroll
    for (int mi = 0; mi < 2; mi++)
#pragma unroll
        for (int q = 0; q < 4; q++) acc[mi][q] = 0.0f;

    // ldmatrix lane addressing
    const uint32_t sbase = smem_u32(smem);
    const int a_row  = warp_m * 32 + (lane & 15);
    const int a_colh = (lane >> 4) * 8;
    const int b_row  = BM + warp_n * 8 + (lane & 7);
    const int b_kh   = ((lane >> 3) & 1) * 8;

#pragma unroll
    for (int kt = 0; kt < 8; kt++) {
        // wait for group kt (7-kt groups may remain pending)
        switch (kt) {
            case 0: cp_wait<7>(); break;
            case 1: cp_wait<6>(); break;
            case 2: cp_wait<5>(); break;
            case 3: cp_wait<4>(); break;
            case 4: cp_wait<3>(); break;
            case 5: cp_wait<2>(); break;
            case 6: cp_wait<1>(); break;
            default: cp_wait<0>(); break;
        }
        __syncthreads();

#pragma unroll
        for (int ks = 0; ks < 4; ks++) {
            const int kk = kt * 64 + ks * 16;
            uint32_t a[2][4];
#pragma unroll
            for (int mi = 0; mi < 2; mi++) {
                uint32_t addr = sbase + ((a_row + mi * 16) * LDSE + kk + a_colh) * 2;
                ldsm_x4(a[mi][0], a[mi][1], a[mi][2], a[mi][3], addr);
            }
            uint32_t b0, b1;
            {
                uint32_t addr = sbase + (b_row * LDSE + kk + b_kh) * 2;
                ldsm_x2(b0, b1, addr);
            }
#pragma unroll
            for (int mi = 0; mi < 2; mi++)
                mma16816(acc[mi][0], acc[mi][1], acc[mi][2], acc[mi][3],
                         a[mi][0], a[mi][1], a[mi][2], a[mi][3], b0, b1);
        }
    }

    // ---- epilogue: zero-point corrections + rescale ----
    const float xs  = xs_p[0];
    const float xzp = xzp_p[0];
    const float ws  = ws_p[0];
    const float wzp = wzp_p[0];
    const float sc  = xs * ws;
    const float kconst = (float)MDIM * xzp * wzp;

    const int col = n0 + warp_n * 8 + (lane & 3) * 2;
    const float cs0 = g_colsum[col];
    const float cs1 = g_colsum[col + 1];

#pragma unroll
    for (int mi = 0; mi < 2; mi++) {
#pragma unroll
        for (int half = 0; half < 2; half++) {
            int row = m0 + warp_m * 32 + mi * 16 + (lane >> 2) + half * 8;
            float rs = g_rowsum[row];
            float corr = -wzp * rs + kconst;
            float v0 = (acc[mi][half * 2 + 0] + corr - xzp * cs0) * sc;
            float v1 = (acc[mi][half * 2 + 1] + corr - xzp * cs1) * sc;
            *reinterpret_cast<float2*>(out + (size_t)row * KDIM + col) =
                make_float2(v0, v1);
        }
    }
}

// ---------------------------------------------------------------------------
// Launch. Inputs: x, w, lut, x_scale, x_zero_point, w_scale, w_zero_point.
// ---------------------------------------------------------------------------
extern "C" void kernel_launch(void* const* d_in, const int* in_sizes, int n_in,
                              void* d_out, int out_size) {
    const float* x   = (const float*)d_in[0];
    const float* w   = (const float*)d_in[1];
    const float* xs  = (const float*)d_in[3];
    const float* xzp = (const float*)d_in[4];
    const float* ws  = (const float*)d_in[5];
    const float* wzp = (const float*)d_in[6];
    float* out = (float*)d_out;

    cudaFuncSetAttribute(lut_gemm_kernel,
                         cudaFuncAttributeMaxDynamicSharedMemorySize, SMEM_BYTES);

    quant_all_kernel<<<TOTROWS / 2, 256>>>(x, w, xs, xzp, ws, wzp);

    dim3 grid(MROWS / BM, KDIM / BN);   // 32 x 8 = 256 blocks
    lut_gemm_kernel<<<grid, 256, SMEM_BYTES>>>(out, xs, xzp, ws, wzp);
}